// round 11
// baseline (speedup 1.0000x reference)
#include <cuda_runtime.h>
#include <cuda_fp16.h>
#include <cstdint>

// ---------------- problem constants ----------------
#define D_DIM 3072
#define N_DIM 8192
#define B_DIM 2

#define TM 128            // CTA M tile (d)
#define TN 128            // CTA N tile (n)
#define TK 64             // K tile (halves) = 128B per row
#define STAGES 3
#define NK (N_DIM / TK)   // 128 k iterations
#define MT (D_DIM / TM)   // 24
#define NT (N_DIM / TN)   // 64

#define TOTAL_TILES (B_DIM * MT * NT)  // 3072
#define MAIN_TILES  3040               // uniform full tiles
#define REM_TILES   (TOTAL_TILES - MAIN_TILES)  // 32
#define KSPLIT      8
#define NK_PART     (NK / KSPLIT)      // 16
#define REM_CTAS    (REM_TILES * KSPLIT)  // 256
#define GRID_TOTAL  (MAIN_TILES + REM_CTAS) // 3296

#define ROWH 72                           // padded row (halves): conflict-free ldmatrix
#define TILE_H (128 * ROWH)               // 9216 halves per 128-row tile
#define STAGE_H (2 * TILE_H)              // A + B per stage = 36864 B
#define SMEM_BYTES (STAGES * STAGE_H * 2) // 110592 B -> 2 CTAs/SM

// fp16 scratch copies of the inputs (zero-init .bss; no runtime allocation)
__device__ __half g_xh[(size_t)B_DIM * D_DIM * N_DIM];
__device__ __half g_adjh[(size_t)B_DIM * N_DIM * N_DIM];
// split-K partials for the 32 remainder tiles
__device__ float g_part[(size_t)REM_TILES * KSPLIT * TM * TN];

// ---------------- PTX helpers ----------------
__device__ __forceinline__ uint32_t smem_u32(const void* p) {
    uint32_t a;
    asm("{ .reg .u64 t; cvta.to.shared.u64 t, %1; cvt.u32.u64 %0, t; }" : "=r"(a) : "l"(p));
    return a;
}
__device__ __forceinline__ void cp_async16(uint32_t saddr, const void* gaddr) {
    asm volatile("cp.async.cg.shared.global [%0], [%1], 16;" :: "r"(saddr), "l"(gaddr) : "memory");
}
#define CP_COMMIT() asm volatile("cp.async.commit_group;" ::: "memory")
#define CP_WAIT(n)  asm volatile("cp.async.wait_group %0;" :: "n"(n) : "memory")

__device__ __forceinline__ void ldmatrix_x4(uint32_t* r, uint32_t addr) {
    asm volatile("ldmatrix.sync.aligned.m8n8.x4.shared.b16 {%0,%1,%2,%3}, [%4];"
        : "=r"(r[0]), "=r"(r[1]), "=r"(r[2]), "=r"(r[3]) : "r"(addr));
}
__device__ __forceinline__ void mma_f16(float& c0, float& c1, float& c2, float& c3,
                                        uint32_t a0, uint32_t a1, uint32_t a2, uint32_t a3,
                                        uint32_t b0, uint32_t b1) {
    asm volatile(
        "mma.sync.aligned.m16n8k16.row.col.f32.f16.f16.f32 "
        "{%0,%1,%2,%3}, {%4,%5,%6,%7}, {%8,%9}, {%0,%1,%2,%3};"
        : "+f"(c0), "+f"(c1), "+f"(c2), "+f"(c3)
        : "r"(a0), "r"(a1), "r"(a2), "r"(a3), "r"(b0), "r"(b1));
}
__device__ __forceinline__ uint32_t pack_h2(float lo, float hi) {
    uint32_t u;
    asm("cvt.rn.f16x2.f32 %0, %1, %2;" : "=r"(u) : "f"(hi), "f"(lo));
    return u;
}
__device__ __forceinline__ float4 ld_cs_f4(const float* p) {
    float4 v;
    asm volatile("ld.global.cs.v4.f32 {%0,%1,%2,%3}, [%4];"
        : "=f"(v.x), "=f"(v.y), "=f"(v.z), "=f"(v.w) : "l"(p));
    return v;
}

// ---------------- prepass: fp32 -> fp16, both tensors, streaming reads ----------------
__global__ void __launch_bounds__(256)
cvt_f2h_both_kernel(const float* __restrict__ x, __half* __restrict__ xh, size_t nx,
                    const float* __restrict__ adj, __half* __restrict__ adjh, size_t na)
{
    const size_t total8 = (nx + na) / 8;
    size_t idx = (size_t)blockIdx.x * blockDim.x + threadIdx.x;
    const size_t stride = (size_t)gridDim.x * blockDim.x;
    const size_t nx8 = nx / 8;
    for (; idx < total8; idx += stride) {
        const float* src;
        __half* dst;
        size_t i;
        if (idx < nx8) { src = x;   dst = xh;   i = idx * 8; }
        else           { src = adj; dst = adjh; i = (idx - nx8) * 8; }
        float4 f0 = ld_cs_f4(src + i);
        float4 f1 = ld_cs_f4(src + i + 4);
        uint4 v;
        v.x = pack_h2(f0.x, f0.y);
        v.y = pack_h2(f0.z, f0.w);
        v.z = pack_h2(f1.x, f1.y);
        v.w = pack_h2(f1.z, f1.w);
        *reinterpret_cast<uint4*>(dst + i) = v;
    }
}

// ---------------- shared GEMM machinery ----------------
struct GemmCtx {
    uint32_t sA_st, sB_st, aOff, bOff, sbase;
    const __half* gA;
    const __half* gB;
};

// one k-iteration with COMPILE-TIME stage indices
template<int CUR>
__device__ __forceinline__ void k_iter(const GemmCtx& cx, int k, int kend,
                                       float (&acc)[4][8][4],
                                       uint32_t (&af)[2][4][4], uint32_t (&bf)[2][4][4])
{
    constexpr int SW = (CUR + 2) % 3;   // write stage (for iter k+2)
    constexpr int SN = (CUR + 1) % 3;   // read stage of next iter
    const bool do_pref = (k + STAGES - 1 < kend);
    const size_t k0 = (size_t)(k + STAGES - 1) * TK;

    const uint32_t aBase = cx.sbase + (uint32_t)(CUR * STAGE_H) * 2 + cx.aOff;
    const uint32_t bBase = cx.sbase + (uint32_t)(CUR * STAGE_H) * 2 + cx.bOff;

    #pragma unroll
    for (int kb = 0; kb < 4; kb++) {
        const int cb = kb & 1;
        const int nb = cb ^ 1;

        // prefetch next kb's fragments (same stage) before this kb's MMAs
        if (kb < 3) {
            const uint32_t kByte = (uint32_t)((kb + 1) * 16 * 2);
            #pragma unroll
            for (int mi = 0; mi < 4; mi++)
                ldmatrix_x4(af[nb][mi], aBase + (uint32_t)(mi * 16 * ROWH * 2) + kByte);
            #pragma unroll
            for (int np = 0; np < 4; np++)
                ldmatrix_x4(bf[nb][np], bBase + (uint32_t)(np * 16 * ROWH * 2) + kByte);
        }

        #pragma unroll
        for (int mi = 0; mi < 4; mi++)
            #pragma unroll
            for (int np = 0; np < 4; np++) {
                mma_f16(acc[mi][2*np][0], acc[mi][2*np][1], acc[mi][2*np][2], acc[mi][2*np][3],
                        af[cb][mi][0], af[cb][mi][1], af[cb][mi][2], af[cb][mi][3],
                        bf[cb][np][0], bf[cb][np][1]);
                mma_f16(acc[mi][2*np+1][0], acc[mi][2*np+1][1], acc[mi][2*np+1][2], acc[mi][2*np+1][3],
                        af[cb][mi][0], af[cb][mi][1], af[cb][mi][2], af[cb][mi][3],
                        bf[cb][np][2], bf[cb][np][3]);
            }

        // spread stage-(k+2) cp.asyncs across kb steps, AFTER this kb's MMAs:
        // kb0 -> A rows 0-63, kb1 -> A rows 64-127, kb2 -> B rows 0-63, kb3 -> B rows 64-127
        if (do_pref) {
            #pragma unroll
            for (int i = 0; i < 4; i++) {
                const int r = (kb & 1) * 4 + i;
                if (kb < 2)
                    cp_async16(cx.sA_st + (uint32_t)(SW * STAGE_H + r * 16 * ROWH) * 2,
                               cx.gA + k0 + (size_t)r * 16 * N_DIM);
                else
                    cp_async16(cx.sB_st + (uint32_t)(SW * STAGE_H + r * 16 * ROWH) * 2,
                               cx.gB + k0 + (size_t)r * 16 * N_DIM);
            }
        }
    }
    CP_COMMIT();

    CP_WAIT(STAGES - 2);
    __syncthreads();

    // preload kb=0 fragments of the next iteration's stage
    if (k + 1 < kend) {
        const uint32_t aB2 = cx.sbase + (uint32_t)(SN * STAGE_H) * 2 + cx.aOff;
        const uint32_t bB2 = cx.sbase + (uint32_t)(SN * STAGE_H) * 2 + cx.bOff;
        #pragma unroll
        for (int mi = 0; mi < 4; mi++)
            ldmatrix_x4(af[0][mi], aB2 + (uint32_t)(mi * 16 * ROWH * 2));
        #pragma unroll
        for (int np = 0; np < 4; np++)
            ldmatrix_x4(bf[0][np], bB2 + (uint32_t)(np * 16 * ROWH * 2));
    }
}

__device__ __forceinline__ void gemm_tile(const GemmCtx& cx, int kbeg, int kend,
                                          float (&acc)[4][8][4])
{
    // prologue: fill stages 0,1
    #pragma unroll
    for (int s = 0; s < STAGES - 1; s++) {
        const size_t k0 = (size_t)(kbeg + s) * TK;
        #pragma unroll
        for (int i = 0; i < 8; i++) {
            cp_async16(cx.sA_st + (uint32_t)(s * STAGE_H + i * 16 * ROWH) * 2, cx.gA + k0 + (size_t)i * 16 * N_DIM);
            cp_async16(cx.sB_st + (uint32_t)(s * STAGE_H + i * 16 * ROWH) * 2, cx.gB + k0 + (size_t)i * 16 * N_DIM);
        }
        CP_COMMIT();
    }
    CP_WAIT(STAGES - 2);
    __syncthreads();

    uint32_t af[2][4][4];
    uint32_t bf[2][4][4];

    // preload kb=0 of stage 0
    {
        const uint32_t aBase = cx.sbase + cx.aOff;
        const uint32_t bBase = cx.sbase + cx.bOff;
        #pragma unroll
        for (int mi = 0; mi < 4; mi++)
            ldmatrix_x4(af[0][mi], aBase + (uint32_t)(mi * 16 * ROWH * 2));
        #pragma unroll
        for (int np = 0; np < 4; np++)
            ldmatrix_x4(bf[0][np], bBase + (uint32_t)(np * 16 * ROWH * 2));
    }

    // triple-unrolled k loop: stage indices are compile-time constants
    for (int k = kbeg; k < kend; ) {
        k_iter<0>(cx, k, kend, acc, af, bf); k++;
        if (k >= kend) break;
        k_iter<1>(cx, k, kend, acc, af, bf); k++;
        if (k >= kend) break;
        k_iter<2>(cx, k, kend, acc, af, bf); k++;
    }
}

__device__ __forceinline__ void make_ctx(GemmCtx& cx, uint32_t sbase, int tid,
                                         int b, int d0, int n0, int wm, int wn)
{
    const int lane = tid & 31;
    const int crow = tid >> 3;
    const int cc   = tid & 7;
    cx.sbase = sbase;
    cx.gA = g_xh   + ((size_t)b * D_DIM + d0 + crow) * N_DIM + cc * 8;
    cx.gB = g_adjh + ((size_t)b * N_DIM + n0 + crow) * N_DIM + cc * 8;
    cx.sA_st = sbase + (uint32_t)(crow * ROWH + cc * 8) * 2;
    cx.sB_st = cx.sA_st + TILE_H * 2;
    cx.aOff = (uint32_t)(((wm + (lane & 15)) * ROWH + (lane >> 4) * 8) * 2);
    cx.bOff = (uint32_t)(((wn + ((lane >> 4) << 3) + (lane & 7)) * ROWH
                          + ((lane >> 3) & 1) * 8) * 2) + TILE_H * 2;
}

// ---------------- merged GEMM kernel: rem CTAs (bx<256) + main tiles (bx>=256) ----------------
__global__ void __launch_bounds__(128, 2)
gcn_f16_mma_kernel(float* __restrict__ out)
{
    extern __shared__ __half smem[];
    const uint32_t sbase = smem_u32(smem);
    const int tid = threadIdx.x;
    const int wid = tid >> 5;
    const int lane = tid & 31;
    const int wm = (wid & 1) * 64;
    const int wn = (wid >> 1) * 64;

    const int bx = blockIdx.x;
    const bool is_rem = (bx < REM_CTAS);

    int tile, kbeg, kend;
    if (is_rem) {
        tile = MAIN_TILES + (bx >> 3);       // 3040..3071
        const int kp = bx & 7;
        kbeg = kp * NK_PART;
        kend = kbeg + NK_PART;
    } else {
        tile = bx - REM_CTAS;                // 0..3039
        kbeg = 0;
        kend = NK;
    }

    const int mt = tile % MT;
    const int nt = (tile / MT) % NT;
    const int b  = tile / (MT * NT);
    const int d0 = mt * TM;
    const int n0 = nt * TN;

    GemmCtx cx;
    make_ctx(cx, sbase, tid, b, d0, n0, wm, wn);

    float acc[4][8][4];
    #pragma unroll
    for (int i = 0; i < 4; i++)
        #pragma unroll
        for (int j = 0; j < 8; j++)
            #pragma unroll
            for (int r = 0; r < 4; r++) acc[i][j][r] = 0.0f;

    gemm_tile(cx, kbeg, kend, acc);

    if (is_rem) {
        // store partials row-major [128][128] into g_part[bx]
        float* pb = g_part + (size_t)bx * (TM * TN);
        #pragma unroll
        for (int mi = 0; mi < 4; mi++) {
            const int r0 = wm + mi * 16 + (lane >> 2);
            #pragma unroll
            for (int ni = 0; ni < 8; ni++) {
                const int c = wn + ni * 8 + (lane & 3) * 2;
                float2 v0 = make_float2(acc[mi][ni][0], acc[mi][ni][1]);
                float2 v1 = make_float2(acc[mi][ni][2], acc[mi][ni][3]);
                *reinterpret_cast<float2*>(pb + (size_t)r0 * TN + c) = v0;
                *reinterpret_cast<float2*>(pb + (size_t)(r0 + 8) * TN + c) = v1;
            }
        }
    } else {
        float* ob = out + ((size_t)b * D_DIM) * N_DIM;
        #pragma unroll
        for (int mi = 0; mi < 4; mi++) {
            const int r0 = d0 + wm + mi * 16 + (lane >> 2);
            #pragma unroll
            for (int ni = 0; ni < 8; ni++) {
                const int c = n0 + wn + ni * 8 + (lane & 3) * 2;
                float2 v0 = make_float2(acc[mi][ni][0], acc[mi][ni][1]);
                float2 v1 = make_float2(acc[mi][ni][2], acc[mi][ni][3]);
                *reinterpret_cast<float2*>(ob + (size_t)r0 * N_DIM + c) = v0;
                *reinterpret_cast<float2*>(ob + (size_t)(r0 + 8) * N_DIM + c) = v1;
            }
        }
    }
}

// ---------------- reduce 8 partials per remainder tile into out ----------------
__global__ void __launch_bounds__(256)
reduce_rem_kernel(float* __restrict__ out)
{
    const int gidx = blockIdx.x * blockDim.x + threadIdx.x;
    const int t   = gidx / (TM * TN / 4);
    const int e4  = gidx % (TM * TN / 4);
    const int e   = e4 * 4;

    const float* pb = g_part + (size_t)t * KSPLIT * (TM * TN) + e;
    float4 s = *reinterpret_cast<const float4*>(pb);
    #pragma unroll
    for (int p = 1; p < KSPLIT; p++) {
        float4 v = *reinterpret_cast<const float4*>(pb + (size_t)p * (TM * TN));
        s.x += v.x; s.y += v.y; s.z += v.z; s.w += v.w;
    }

    const int tile = MAIN_TILES + t;
    const int mt = tile % MT;
    const int nt = (tile / MT) % NT;
    const int b  = tile / (MT * NT);
    const int row = e / TN;
    const int col = e % TN;
    float* op = out + ((size_t)b * D_DIM + mt * TM + row) * N_DIM + nt * TN + col;
    *reinterpret_cast<float4*>(op) = s;
}

// ---------------- host launch ----------------
extern "C" void kernel_launch(void* const* d_in, const int* in_sizes, int n_in,
                              void* d_out, int out_size)
{
    const float* x;
    const float* adj;
    if (in_sizes[0] == B_DIM * D_DIM * N_DIM) {
        x = (const float*)d_in[0]; adj = (const float*)d_in[1];
    } else {
        x = (const float*)d_in[1]; adj = (const float*)d_in[0];
    }

    __half* xh;
    __half* adjh;
    cudaGetSymbolAddress((void**)&xh, g_xh);
    cudaGetSymbolAddress((void**)&adjh, g_adjh);

    const size_t nx = (size_t)B_DIM * D_DIM * N_DIM;
    const size_t na = (size_t)B_DIM * N_DIM * N_DIM;
    cvt_f2h_both_kernel<<<6080, 256>>>(x, xh, nx, adj, adjh, na);

    cudaFuncSetAttribute(gcn_f16_mma_kernel, cudaFuncAttributeMaxDynamicSharedMemorySize, SMEM_BYTES);
    gcn_f16_mma_kernel<<<GRID_TOTAL, 128, SMEM_BYTES>>>((float*)d_out);
    reduce_rem_kernel<<<(REM_TILES * TM * TN / 4) / 256, 256>>>((float*)d_out);
}

// round 12
// speedup vs baseline: 1.0112x; 1.0112x over previous
#include <cuda_runtime.h>
#include <cuda_fp16.h>
#include <cstdint>

// ---------------- problem constants ----------------
#define D_DIM 3072
#define N_DIM 8192
#define B_DIM 2

#define TM 128            // CTA M tile (d)
#define TN 128            // CTA N tile (n)
#define TK 64             // K tile (halves) = 128B per row
#define STAGES 3
#define NK (N_DIM / TK)   // 128 k iterations
#define MT (D_DIM / TM)   // 24
#define NT (N_DIM / TN)   // 64

#define TOTAL_TILES (B_DIM * MT * NT)  // 3072
#define MAIN_TILES  3040               // uniform full tiles
#define REM_TILES   (TOTAL_TILES - MAIN_TILES)  // 32
#define KSPLIT      8
#define NK_PART     (NK / KSPLIT)      // 16
#define REM_CTAS    (REM_TILES * KSPLIT)  // 256
#define GRID_TOTAL  (MAIN_TILES + REM_CTAS) // 3296

#define ROWH 72                           // padded row (halves): conflict-free ldmatrix
#define TILE_H (128 * ROWH)               // 9216 halves per 128-row tile
#define STAGE_H (2 * TILE_H)              // A + B per stage = 36864 B
#define SMEM_BYTES (STAGES * STAGE_H * 2) // 110592 B -> 2 CTAs/SM

// fp16 scratch copies of the inputs (zero-init .bss; no runtime allocation)
__device__ __half g_xh[(size_t)B_DIM * D_DIM * N_DIM];
__device__ __half g_adjh[(size_t)B_DIM * N_DIM * N_DIM];
// split-K partials for the 32 remainder tiles
__device__ float g_part[(size_t)REM_TILES * KSPLIT * TM * TN];

// ---------------- PTX helpers ----------------
__device__ __forceinline__ uint32_t smem_u32(const void* p) {
    uint32_t a;
    asm("{ .reg .u64 t; cvta.to.shared.u64 t, %1; cvt.u32.u64 %0, t; }" : "=r"(a) : "l"(p));
    return a;
}
__device__ __forceinline__ void cp_async16(uint32_t saddr, const void* gaddr) {
    asm volatile("cp.async.cg.shared.global [%0], [%1], 16;" :: "r"(saddr), "l"(gaddr) : "memory");
}
#define CP_COMMIT() asm volatile("cp.async.commit_group;" ::: "memory")
#define CP_WAIT(n)  asm volatile("cp.async.wait_group %0;" :: "n"(n) : "memory")

__device__ __forceinline__ void ldmatrix_x4(uint32_t* r, uint32_t addr) {
    asm volatile("ldmatrix.sync.aligned.m8n8.x4.shared.b16 {%0,%1,%2,%3}, [%4];"
        : "=r"(r[0]), "=r"(r[1]), "=r"(r[2]), "=r"(r[3]) : "r"(addr));
}
__device__ __forceinline__ void mma_f16(float& c0, float& c1, float& c2, float& c3,
                                        uint32_t a0, uint32_t a1, uint32_t a2, uint32_t a3,
                                        uint32_t b0, uint32_t b1) {
    asm volatile(
        "mma.sync.aligned.m16n8k16.row.col.f32.f16.f16.f32 "
        "{%0,%1,%2,%3}, {%4,%5,%6,%7}, {%8,%9}, {%0,%1,%2,%3};"
        : "+f"(c0), "+f"(c1), "+f"(c2), "+f"(c3)
        : "r"(a0), "r"(a1), "r"(a2), "r"(a3), "r"(b0), "r"(b1));
}
__device__ __forceinline__ uint32_t pack_h2(float lo, float hi) {
    uint32_t u;
    asm("cvt.rn.f16x2.f32 %0, %1, %2;" : "=r"(u) : "f"(hi), "f"(lo));
    return u;
}
__device__ __forceinline__ void st_cs_f2(float* p, float2 v) {
    asm volatile("st.global.cs.v2.f32 [%0], {%1,%2};" :: "l"(p), "f"(v.x), "f"(v.y) : "memory");
}

// ---------------- prepass: fp32 -> fp16, both tensors, MLP=4 ----------------
__global__ void __launch_bounds__(256)
cvt_f2h_both_kernel(const float* __restrict__ x, __half* __restrict__ xh, size_t nx,
                    const float* __restrict__ adj, __half* __restrict__ adjh, size_t na)
{
    // process 16 floats (4 x float4) per thread per step
    const size_t total16 = (nx + na) / 16;
    size_t idx = (size_t)blockIdx.x * blockDim.x + threadIdx.x;
    const size_t stride = (size_t)gridDim.x * blockDim.x;
    const size_t nx16 = nx / 16;
    for (; idx < total16; idx += stride) {
        const float* src;
        __half* dst;
        size_t i;
        if (idx < nx16) { src = x;   dst = xh;   i = idx * 16; }
        else            { src = adj; dst = adjh; i = (idx - nx16) * 16; }
        float4 f0 = *reinterpret_cast<const float4*>(src + i);
        float4 f1 = *reinterpret_cast<const float4*>(src + i + 4);
        float4 f2 = *reinterpret_cast<const float4*>(src + i + 8);
        float4 f3 = *reinterpret_cast<const float4*>(src + i + 12);
        uint4 v0, v1;
        v0.x = pack_h2(f0.x, f0.y);  v0.y = pack_h2(f0.z, f0.w);
        v0.z = pack_h2(f1.x, f1.y);  v0.w = pack_h2(f1.z, f1.w);
        v1.x = pack_h2(f2.x, f2.y);  v1.y = pack_h2(f2.z, f2.w);
        v1.z = pack_h2(f3.x, f3.y);  v1.w = pack_h2(f3.z, f3.w);
        *reinterpret_cast<uint4*>(dst + i)     = v0;
        *reinterpret_cast<uint4*>(dst + i + 8) = v1;
    }
}

// ---------------- shared GEMM body (R10 proven version: dynamic stage indices) ----------------
struct GemmCtx {
    uint32_t sA_st, sB_st, aOff, bOff, sbase;
    const __half* gA;
    const __half* gB;
};

__device__ __forceinline__ void gemm_tile(const GemmCtx& cx, int kbeg, int kend,
                                          float (&acc)[4][8][4])
{
    const uint32_t sbase = cx.sbase;
    // prologue
    #pragma unroll
    for (int s = 0; s < STAGES - 1; s++) {
        const size_t k0 = (size_t)(kbeg + s) * TK;
        #pragma unroll
        for (int i = 0; i < 8; i++) {
            cp_async16(cx.sA_st + (uint32_t)(s * STAGE_H + i * 16 * ROWH) * 2, cx.gA + k0 + (size_t)i * 16 * N_DIM);
            cp_async16(cx.sB_st + (uint32_t)(s * STAGE_H + i * 16 * ROWH) * 2, cx.gB + k0 + (size_t)i * 16 * N_DIM);
        }
        CP_COMMIT();
    }
    CP_WAIT(STAGES - 2);
    __syncthreads();

    uint32_t af[2][4][4];
    uint32_t bf[2][4][4];

    // preload kb=0 of first stage
    {
        const uint32_t aBase = sbase + cx.aOff;
        const uint32_t bBase = sbase + cx.bOff;
        #pragma unroll
        for (int mi = 0; mi < 4; mi++)
            ldmatrix_x4(af[0][mi], aBase + (uint32_t)(mi * 16 * ROWH * 2));
        #pragma unroll
        for (int np = 0; np < 4; np++)
            ldmatrix_x4(bf[0][np], bBase + (uint32_t)(np * 16 * ROWH * 2));
    }

    for (int k = kbeg; k < kend; k++) {
        const int cur = (k - kbeg) % STAGES;
        const bool do_pref = (k + STAGES - 1 < kend);
        const int s = (k - kbeg + STAGES - 1) % STAGES;
        const size_t k0 = (size_t)(k + STAGES - 1) * TK;

        const uint32_t aBase = sbase + (uint32_t)(cur * STAGE_H) * 2 + cx.aOff;
        const uint32_t bBase = sbase + (uint32_t)(cur * STAGE_H) * 2 + cx.bOff;

        #pragma unroll
        for (int kb = 0; kb < 4; kb++) {
            const int cb = kb & 1;
            const int nb = cb ^ 1;

            if (kb < 3) {
                const uint32_t kByte = (uint32_t)((kb + 1) * 16 * 2);
                #pragma unroll
                for (int mi = 0; mi < 4; mi++)
                    ldmatrix_x4(af[nb][mi], aBase + (uint32_t)(mi * 16 * ROWH * 2) + kByte);
                #pragma unroll
                for (int np = 0; np < 4; np++)
                    ldmatrix_x4(bf[nb][np], bBase + (uint32_t)(np * 16 * ROWH * 2) + kByte);
            }

            #pragma unroll
            for (int mi = 0; mi < 4; mi++)
                #pragma unroll
                for (int np = 0; np < 4; np++) {
                    mma_f16(acc[mi][2*np][0], acc[mi][2*np][1], acc[mi][2*np][2], acc[mi][2*np][3],
                            af[cb][mi][0], af[cb][mi][1], af[cb][mi][2], af[cb][mi][3],
                            bf[cb][np][0], bf[cb][np][1]);
                    mma_f16(acc[mi][2*np+1][0], acc[mi][2*np+1][1], acc[mi][2*np+1][2], acc[mi][2*np+1][3],
                            af[cb][mi][0], af[cb][mi][1], af[cb][mi][2], af[cb][mi][3],
                            bf[cb][np][2], bf[cb][np][3]);
                }

            // spread next-stage cp.asyncs across kb steps, after this kb's MMAs
            if (do_pref) {
                #pragma unroll
                for (int i = 0; i < 4; i++) {
                    const int r = (kb & 1) * 4 + i;
                    if (kb < 2)
                        cp_async16(cx.sA_st + (uint32_t)(s * STAGE_H + r * 16 * ROWH) * 2,
                                   cx.gA + k0 + (size_t)r * 16 * N_DIM);
                    else
                        cp_async16(cx.sB_st + (uint32_t)(s * STAGE_H + r * 16 * ROWH) * 2,
                                   cx.gB + k0 + (size_t)r * 16 * N_DIM);
                }
            }
        }
        CP_COMMIT();

        CP_WAIT(STAGES - 2);
        __syncthreads();

        if (k + 1 < kend) {
            const int nxt = (k + 1 - kbeg) % STAGES;
            const uint32_t aB2 = sbase + (uint32_t)(nxt * STAGE_H) * 2 + cx.aOff;
            const uint32_t bB2 = sbase + (uint32_t)(nxt * STAGE_H) * 2 + cx.bOff;
            #pragma unroll
            for (int mi = 0; mi < 4; mi++)
                ldmatrix_x4(af[0][mi], aB2 + (uint32_t)(mi * 16 * ROWH * 2));
            #pragma unroll
            for (int np = 0; np < 4; np++)
                ldmatrix_x4(bf[0][np], bB2 + (uint32_t)(np * 16 * ROWH * 2));
        }
    }
}

__device__ __forceinline__ void make_ctx(GemmCtx& cx, uint32_t sbase, int tid,
                                         int b, int d0, int n0, int wm, int wn)
{
    const int lane = tid & 31;
    const int crow = tid >> 3;
    const int cc   = tid & 7;
    cx.sbase = sbase;
    cx.gA = g_xh   + ((size_t)b * D_DIM + d0 + crow) * N_DIM + cc * 8;
    cx.gB = g_adjh + ((size_t)b * N_DIM + n0 + crow) * N_DIM + cc * 8;
    cx.sA_st = sbase + (uint32_t)(crow * ROWH + cc * 8) * 2;
    cx.sB_st = cx.sA_st + TILE_H * 2;
    cx.aOff = (uint32_t)(((wm + (lane & 15)) * ROWH + (lane >> 4) * 8) * 2);
    cx.bOff = (uint32_t)(((wn + ((lane >> 4) << 3) + (lane & 7)) * ROWH
                          + ((lane >> 3) & 1) * 8) * 2) + TILE_H * 2;
}

// ---------------- merged GEMM kernel: rem CTAs (bx<256) + main tiles (bx>=256) ----------------
__global__ void __launch_bounds__(128, 2)
gcn_f16_mma_kernel(float* __restrict__ out)
{
    extern __shared__ __half smem[];
    const uint32_t sbase = smem_u32(smem);
    const int tid = threadIdx.x;
    const int wid = tid >> 5;
    const int lane = tid & 31;
    const int wm = (wid & 1) * 64;
    const int wn = (wid >> 1) * 64;

    const int bx = blockIdx.x;
    const bool is_rem = (bx < REM_CTAS);

    int tile, kbeg, kend;
    if (is_rem) {
        tile = MAIN_TILES + (bx >> 3);       // 3040..3071
        const int kp = bx & 7;
        kbeg = kp * NK_PART;
        kend = kbeg + NK_PART;
    } else {
        tile = bx - REM_CTAS;                // 0..3039
        kbeg = 0;
        kend = NK;
    }

    const int mt = tile % MT;
    const int nt = (tile / MT) % NT;
    const int b  = tile / (MT * NT);
    const int d0 = mt * TM;
    const int n0 = nt * TN;

    GemmCtx cx;
    make_ctx(cx, sbase, tid, b, d0, n0, wm, wn);

    float acc[4][8][4];
    #pragma unroll
    for (int i = 0; i < 4; i++)
        #pragma unroll
        for (int j = 0; j < 8; j++)
            #pragma unroll
            for (int r = 0; r < 4; r++) acc[i][j][r] = 0.0f;

    gemm_tile(cx, kbeg, kend, acc);

    if (is_rem) {
        // store partials row-major [128][128] into g_part[bx]
        float* pb = g_part + (size_t)bx * (TM * TN);
        #pragma unroll
        for (int mi = 0; mi < 4; mi++) {
            const int r0 = wm + mi * 16 + (lane >> 2);
            #pragma unroll
            for (int ni = 0; ni < 8; ni++) {
                const int c = wn + ni * 8 + (lane & 3) * 2;
                float2 v0 = make_float2(acc[mi][ni][0], acc[mi][ni][1]);
                float2 v1 = make_float2(acc[mi][ni][2], acc[mi][ni][3]);
                *reinterpret_cast<float2*>(pb + (size_t)r0 * TN + c) = v0;
                *reinterpret_cast<float2*>(pb + (size_t)(r0 + 8) * TN + c) = v1;
            }
        }
    } else {
        float* ob = out + ((size_t)b * D_DIM) * N_DIM;
        #pragma unroll
        for (int mi = 0; mi < 4; mi++) {
            const int r0 = d0 + wm + mi * 16 + (lane >> 2);
            #pragma unroll
            for (int ni = 0; ni < 8; ni++) {
                const int c = n0 + wn + ni * 8 + (lane & 3) * 2;
                st_cs_f2(ob + (size_t)r0 * N_DIM + c,       make_float2(acc[mi][ni][0], acc[mi][ni][1]));
                st_cs_f2(ob + (size_t)(r0 + 8) * N_DIM + c, make_float2(acc[mi][ni][2], acc[mi][ni][3]));
            }
        }
    }
}

// ---------------- reduce 8 partials per remainder tile into out ----------------
__global__ void __launch_bounds__(256)
reduce_rem_kernel(float* __restrict__ out)
{
    const int gidx = blockIdx.x * blockDim.x + threadIdx.x;
    const int t   = gidx / (TM * TN / 4);
    const int e4  = gidx % (TM * TN / 4);
    const int e   = e4 * 4;

    const float* pb = g_part + (size_t)t * KSPLIT * (TM * TN) + e;
    float4 s = *reinterpret_cast<const float4*>(pb);
    #pragma unroll
    for (int p = 1; p < KSPLIT; p++) {
        float4 v = *reinterpret_cast<const float4*>(pb + (size_t)p * (TM * TN));
        s.x += v.x; s.y += v.y; s.z += v.z; s.w += v.w;
    }

    const int tile = MAIN_TILES + t;
    const int mt = tile % MT;
    const int nt = (tile / MT) % NT;
    const int b  = tile / (MT * NT);
    const int row = e / TN;
    const int col = e % TN;
    float* op = out + ((size_t)b * D_DIM + mt * TM + row) * N_DIM + nt * TN + col;
    *reinterpret_cast<float4*>(op) = s;
}

// ---------------- host launch ----------------
extern "C" void kernel_launch(void* const* d_in, const int* in_sizes, int n_in,
                              void* d_out, int out_size)
{
    const float* x;
    const float* adj;
    if (in_sizes[0] == B_DIM * D_DIM * N_DIM) {
        x = (const float*)d_in[0]; adj = (const float*)d_in[1];
    } else {
        x = (const float*)d_in[1]; adj = (const float*)d_in[0];
    }

    __half* xh;
    __half* adjh;
    cudaGetSymbolAddress((void**)&xh, g_xh);
    cudaGetSymbolAddress((void**)&adjh, g_adjh);

    const size_t nx = (size_t)B_DIM * D_DIM * N_DIM;
    const size_t na = (size_t)B_DIM * N_DIM * N_DIM;
    cvt_f2h_both_kernel<<<4096, 256>>>(x, xh, nx, adj, adjh, na);

    cudaFuncSetAttribute(gcn_f16_mma_kernel, cudaFuncAttributeMaxDynamicSharedMemorySize, SMEM_BYTES);
    gcn_f16_mma_kernel<<<GRID_TOTAL, 128, SMEM_BYTES>>>((float*)d_out);
    reduce_rem_kernel<<<(REM_TILES * TM * TN / 4) / 256, 256>>>((float*)d_out);
}

// round 13
// speedup vs baseline: 1.0234x; 1.0120x over previous
#include <cuda_runtime.h>
#include <cuda_fp16.h>
#include <cstdint>

// ---------------- problem constants ----------------
#define D_DIM 3072
#define N_DIM 8192
#define B_DIM 2

#define TM 128            // CTA M tile (d)
#define TN 128            // CTA N tile (n)
#define TK 64             // K tile (halves) = 128B per row
#define STAGES 3
#define NK (N_DIM / TK)   // 128 k iterations
#define MT (D_DIM / TM)   // 24
#define NT (N_DIM / TN)   // 64

#define TOTAL_TILES (B_DIM * MT * NT)  // 3072
#define MAIN_TILES  3040               // uniform full tiles
#define REM_TILES   (TOTAL_TILES - MAIN_TILES)  // 32
#define KSPLIT      8
#define NK_PART     (NK / KSPLIT)      // 16
#define REM_CTAS    (REM_TILES * KSPLIT)  // 256
#define GRID_TOTAL  (MAIN_TILES + REM_CTAS) // 3296

#define ROWH 72                           // padded row (halves): conflict-free ldmatrix
#define TILE_H (128 * ROWH)               // 9216 halves per 128-row tile
#define STAGE_H (2 * TILE_H)              // A + B per stage = 36864 B
#define SMEM_BYTES (STAGES * STAGE_H * 2) // 110592 B -> 2 CTAs/SM

// fp16 scratch copies of the inputs (zero-init .bss; no runtime allocation)
__device__ __half g_xh[(size_t)B_DIM * D_DIM * N_DIM];
__device__ __half g_adjh[(size_t)B_DIM * N_DIM * N_DIM];
// split-K partials for the 32 remainder tiles
__device__ float g_part[(size_t)REM_TILES * KSPLIT * TM * TN];

// ---------------- PTX helpers ----------------
__device__ __forceinline__ uint32_t smem_u32(const void* p) {
    uint32_t a;
    asm("{ .reg .u64 t; cvta.to.shared.u64 t, %1; cvt.u32.u64 %0, t; }" : "=r"(a) : "l"(p));
    return a;
}
__device__ __forceinline__ void cp_async16(uint32_t saddr, const void* gaddr) {
    asm volatile("cp.async.cg.shared.global [%0], [%1], 16;" :: "r"(saddr), "l"(gaddr) : "memory");
}
#define CP_COMMIT() asm volatile("cp.async.commit_group;" ::: "memory")
#define CP_WAIT(n)  asm volatile("cp.async.wait_group %0;" :: "n"(n) : "memory")

__device__ __forceinline__ void ldmatrix_x4(uint32_t* r, uint32_t addr) {
    asm volatile("ldmatrix.sync.aligned.m8n8.x4.shared.b16 {%0,%1,%2,%3}, [%4];"
        : "=r"(r[0]), "=r"(r[1]), "=r"(r[2]), "=r"(r[3]) : "r"(addr));
}
__device__ __forceinline__ void mma_f16(float& c0, float& c1, float& c2, float& c3,
                                        uint32_t a0, uint32_t a1, uint32_t a2, uint32_t a3,
                                        uint32_t b0, uint32_t b1) {
    asm volatile(
        "mma.sync.aligned.m16n8k16.row.col.f32.f16.f16.f32 "
        "{%0,%1,%2,%3}, {%4,%5,%6,%7}, {%8,%9}, {%0,%1,%2,%3};"
        : "+f"(c0), "+f"(c1), "+f"(c2), "+f"(c3)
        : "r"(a0), "r"(a1), "r"(a2), "r"(a3), "r"(b0), "r"(b1));
}
__device__ __forceinline__ uint32_t pack_h2(float lo, float hi) {
    uint32_t u;
    asm("cvt.rn.f16x2.f32 %0, %1, %2;" : "=r"(u) : "f"(hi), "f"(lo));
    return u;
}

// ---------------- prepass: fp32 -> fp16, both tensors (R10 proven form) ----------------
__global__ void __launch_bounds__(256)
cvt_f2h_both_kernel(const float* __restrict__ x, __half* __restrict__ xh, size_t nx,
                    const float* __restrict__ adj, __half* __restrict__ adjh, size_t na)
{
    const size_t total8 = (nx + na) / 8;
    size_t idx = (size_t)blockIdx.x * blockDim.x + threadIdx.x;
    const size_t stride = (size_t)gridDim.x * blockDim.x;
    const size_t nx8 = nx / 8;
    for (; idx < total8; idx += stride) {
        const float* src;
        __half* dst;
        size_t i;
        if (idx < nx8) { src = x;   dst = xh;   i = idx * 8; }
        else           { src = adj; dst = adjh; i = (idx - nx8) * 8; }
        float4 f0 = *reinterpret_cast<const float4*>(src + i);
        float4 f1 = *reinterpret_cast<const float4*>(src + i + 4);
        uint4 v;
        v.x = pack_h2(f0.x, f0.y);
        v.y = pack_h2(f0.z, f0.w);
        v.z = pack_h2(f1.x, f1.y);
        v.w = pack_h2(f1.z, f1.w);
        *reinterpret_cast<uint4*>(dst + i) = v;
    }
}

// ---------------- shared GEMM body (R10 proven version) ----------------
struct GemmCtx {
    uint32_t sA_st, sB_st, aOff, bOff, sbase;
    const __half* gA;
    const __half* gB;
};

__device__ __forceinline__ void gemm_tile(const GemmCtx& cx, int kbeg, int kend,
                                          float (&acc)[4][8][4])
{
    const uint32_t sbase = cx.sbase;
    // prologue
    #pragma unroll
    for (int s = 0; s < STAGES - 1; s++) {
        const size_t k0 = (size_t)(kbeg + s) * TK;
        #pragma unroll
        for (int i = 0; i < 8; i++) {
            cp_async16(cx.sA_st + (uint32_t)(s * STAGE_H + i * 16 * ROWH) * 2, cx.gA + k0 + (size_t)i * 16 * N_DIM);
            cp_async16(cx.sB_st + (uint32_t)(s * STAGE_H + i * 16 * ROWH) * 2, cx.gB + k0 + (size_t)i * 16 * N_DIM);
        }
        CP_COMMIT();
    }
    CP_WAIT(STAGES - 2);
    __syncthreads();

    uint32_t af[2][4][4];
    uint32_t bf[2][4][4];

    // preload kb=0 of first stage
    {
        const uint32_t aBase = sbase + cx.aOff;
        const uint32_t bBase = sbase + cx.bOff;
        #pragma unroll
        for (int mi = 0; mi < 4; mi++)
            ldmatrix_x4(af[0][mi], aBase + (uint32_t)(mi * 16 * ROWH * 2));
        #pragma unroll
        for (int np = 0; np < 4; np++)
            ldmatrix_x4(bf[0][np], bBase + (uint32_t)(np * 16 * ROWH * 2));
    }

    for (int k = kbeg; k < kend; k++) {
        const int cur = (k - kbeg) % STAGES;
        const bool do_pref = (k + STAGES - 1 < kend);
        const int s = (k - kbeg + STAGES - 1) % STAGES;
        const size_t k0 = (size_t)(k + STAGES - 1) * TK;

        const uint32_t aBase = sbase + (uint32_t)(cur * STAGE_H) * 2 + cx.aOff;
        const uint32_t bBase = sbase + (uint32_t)(cur * STAGE_H) * 2 + cx.bOff;

        #pragma unroll
        for (int kb = 0; kb < 4; kb++) {
            const int cb = kb & 1;
            const int nb = cb ^ 1;

            if (kb < 3) {
                const uint32_t kByte = (uint32_t)((kb + 1) * 16 * 2);
                #pragma unroll
                for (int mi = 0; mi < 4; mi++)
                    ldmatrix_x4(af[nb][mi], aBase + (uint32_t)(mi * 16 * ROWH * 2) + kByte);
                #pragma unroll
                for (int np = 0; np < 4; np++)
                    ldmatrix_x4(bf[nb][np], bBase + (uint32_t)(np * 16 * ROWH * 2) + kByte);
            }

            #pragma unroll
            for (int mi = 0; mi < 4; mi++)
                #pragma unroll
                for (int np = 0; np < 4; np++) {
                    mma_f16(acc[mi][2*np][0], acc[mi][2*np][1], acc[mi][2*np][2], acc[mi][2*np][3],
                            af[cb][mi][0], af[cb][mi][1], af[cb][mi][2], af[cb][mi][3],
                            bf[cb][np][0], bf[cb][np][1]);
                    mma_f16(acc[mi][2*np+1][0], acc[mi][2*np+1][1], acc[mi][2*np+1][2], acc[mi][2*np+1][3],
                            af[cb][mi][0], af[cb][mi][1], af[cb][mi][2], af[cb][mi][3],
                            bf[cb][np][2], bf[cb][np][3]);
                }

            // spread next-stage cp.asyncs across kb steps, after this kb's MMAs
            if (do_pref) {
                #pragma unroll
                for (int i = 0; i < 4; i++) {
                    const int r = (kb & 1) * 4 + i;
                    if (kb < 2)
                        cp_async16(cx.sA_st + (uint32_t)(s * STAGE_H + r * 16 * ROWH) * 2,
                                   cx.gA + k0 + (size_t)r * 16 * N_DIM);
                    else
                        cp_async16(cx.sB_st + (uint32_t)(s * STAGE_H + r * 16 * ROWH) * 2,
                                   cx.gB + k0 + (size_t)r * 16 * N_DIM);
                }
            }
        }
        CP_COMMIT();

        CP_WAIT(STAGES - 2);
        __syncthreads();

        if (k + 1 < kend) {
            const int nxt = (k + 1 - kbeg) % STAGES;
            const uint32_t aB2 = sbase + (uint32_t)(nxt * STAGE_H) * 2 + cx.aOff;
            const uint32_t bB2 = sbase + (uint32_t)(nxt * STAGE_H) * 2 + cx.bOff;
            #pragma unroll
            for (int mi = 0; mi < 4; mi++)
                ldmatrix_x4(af[0][mi], aB2 + (uint32_t)(mi * 16 * ROWH * 2));
            #pragma unroll
            for (int np = 0; np < 4; np++)
                ldmatrix_x4(bf[0][np], bB2 + (uint32_t)(np * 16 * ROWH * 2));
        }
    }
}

__device__ __forceinline__ void make_ctx(GemmCtx& cx, uint32_t sbase, int tid,
                                         int b, int d0, int n0, int wm, int wn)
{
    const int lane = tid & 31;
    const int crow = tid >> 3;
    const int cc   = tid & 7;
    cx.sbase = sbase;
    cx.gA = g_xh   + ((size_t)b * D_DIM + d0 + crow) * N_DIM + cc * 8;
    cx.gB = g_adjh + ((size_t)b * N_DIM + n0 + crow) * N_DIM + cc * 8;
    cx.sA_st = sbase + (uint32_t)(crow * ROWH + cc * 8) * 2;
    cx.sB_st = cx.sA_st + TILE_H * 2;
    cx.aOff = (uint32_t)(((wm + (lane & 15)) * ROWH + (lane >> 4) * 8) * 2);
    cx.bOff = (uint32_t)(((wn + ((lane >> 4) << 3) + (lane & 7)) * ROWH
                          + ((lane >> 3) & 1) * 8) * 2) + TILE_H * 2;
}

// ---------------- merged GEMM kernel: main tiles FIRST (bx<3040), rem CTAs LAST ----------------
// rem-last: the launch's tail consists of 1/8-tile chunks so slots draining their
// final main tile backfill with fine-grained work -> smoother makespan tail.
__global__ void __launch_bounds__(128, 2)
gcn_f16_mma_kernel(float* __restrict__ out)
{
    extern __shared__ __half smem[];
    const uint32_t sbase = smem_u32(smem);
    const int tid = threadIdx.x;
    const int wid = tid >> 5;
    const int lane = tid & 31;
    const int wm = (wid & 1) * 64;
    const int wn = (wid >> 1) * 64;

    const int bx = blockIdx.x;
    const bool is_rem = (bx >= MAIN_TILES);

    int tile, kbeg, kend;
    if (is_rem) {
        const int rix = bx - MAIN_TILES;     // 0..255
        tile = MAIN_TILES + (rix >> 3);      // 3040..3071
        const int kp = rix & 7;
        kbeg = kp * NK_PART;
        kend = kbeg + NK_PART;
    } else {
        tile = bx;                           // 0..3039
        kbeg = 0;
        kend = NK;
    }

    const int mt = tile % MT;
    const int nt = (tile / MT) % NT;
    const int b  = tile / (MT * NT);
    const int d0 = mt * TM;
    const int n0 = nt * TN;

    GemmCtx cx;
    make_ctx(cx, sbase, tid, b, d0, n0, wm, wn);

    float acc[4][8][4];
    #pragma unroll
    for (int i = 0; i < 4; i++)
        #pragma unroll
        for (int j = 0; j < 8; j++)
            #pragma unroll
            for (int r = 0; r < 4; r++) acc[i][j][r] = 0.0f;

    gemm_tile(cx, kbeg, kend, acc);

    if (is_rem) {
        // store partials row-major [128][128] into g_part[rix]
        float* pb = g_part + (size_t)(bx - MAIN_TILES) * (TM * TN);
        #pragma unroll
        for (int mi = 0; mi < 4; mi++) {
            const int r0 = wm + mi * 16 + (lane >> 2);
            #pragma unroll
            for (int ni = 0; ni < 8; ni++) {
                const int c = wn + ni * 8 + (lane & 3) * 2;
                float2 v0 = make_float2(acc[mi][ni][0], acc[mi][ni][1]);
                float2 v1 = make_float2(acc[mi][ni][2], acc[mi][ni][3]);
                *reinterpret_cast<float2*>(pb + (size_t)r0 * TN + c) = v0;
                *reinterpret_cast<float2*>(pb + (size_t)(r0 + 8) * TN + c) = v1;
            }
        }
    } else {
        float* ob = out + ((size_t)b * D_DIM) * N_DIM;
        #pragma unroll
        for (int mi = 0; mi < 4; mi++) {
            const int r0 = d0 + wm + mi * 16 + (lane >> 2);
            #pragma unroll
            for (int ni = 0; ni < 8; ni++) {
                const int c = n0 + wn + ni * 8 + (lane & 3) * 2;
                float2 v0 = make_float2(acc[mi][ni][0], acc[mi][ni][1]);
                float2 v1 = make_float2(acc[mi][ni][2], acc[mi][ni][3]);
                *reinterpret_cast<float2*>(ob + (size_t)r0 * N_DIM + c) = v0;
                *reinterpret_cast<float2*>(ob + (size_t)(r0 + 8) * N_DIM + c) = v1;
            }
        }
    }
}

// ---------------- reduce 8 partials per remainder tile into out ----------------
__global__ void __launch_bounds__(256)
reduce_rem_kernel(float* __restrict__ out)
{
    const int gidx = blockIdx.x * blockDim.x + threadIdx.x;
    const int t   = gidx / (TM * TN / 4);
    const int e4  = gidx % (TM * TN / 4);
    const int e   = e4 * 4;

    const float* pb = g_part + (size_t)t * KSPLIT * (TM * TN) + e;
    float4 s = *reinterpret_cast<const float4*>(pb);
    #pragma unroll
    for (int p = 1; p < KSPLIT; p++) {
        float4 v = *reinterpret_cast<const float4*>(pb + (size_t)p * (TM * TN));
        s.x += v.x; s.y += v.y; s.z += v.z; s.w += v.w;
    }

    const int tile = MAIN_TILES + t;
    const int mt = tile % MT;
    const int nt = (tile / MT) % NT;
    const int b  = tile / (MT * NT);
    const int row = e / TN;
    const int col = e % TN;
    float* op = out + ((size_t)b * D_DIM + mt * TM + row) * N_DIM + nt * TN + col;
    *reinterpret_cast<float4*>(op) = s;
}

// ---------------- host launch ----------------
extern "C" void kernel_launch(void* const* d_in, const int* in_sizes, int n_in,
                              void* d_out, int out_size)
{
    const float* x;
    const float* adj;
    if (in_sizes[0] == B_DIM * D_DIM * N_DIM) {
        x = (const float*)d_in[0]; adj = (const float*)d_in[1];
    } else {
        x = (const float*)d_in[1]; adj = (const float*)d_in[0];
    }

    __half* xh;
    __half* adjh;
    cudaGetSymbolAddress((void**)&xh, g_xh);
    cudaGetSymbolAddress((void**)&adjh, g_adjh);

    const size_t nx = (size_t)B_DIM * D_DIM * N_DIM;
    const size_t na = (size_t)B_DIM * N_DIM * N_DIM;
    cvt_f2h_both_kernel<<<6080, 256>>>(x, xh, nx, adj, adjh, na);

    cudaFuncSetAttribute(gcn_f16_mma_kernel, cudaFuncAttributeMaxDynamicSharedMemorySize, SMEM_BYTES);
    gcn_f16_mma_kernel<<<GRID_TOTAL, 128, SMEM_BYTES>>>((float*)d_out);
    reduce_rem_kernel<<<(REM_TILES * TM * TN / 4) / 256, 256>>>((float*)d_out);
}

// round 14
// speedup vs baseline: 1.0250x; 1.0016x over previous
#include <cuda_runtime.h>
#include <cuda_fp16.h>
#include <cstdint>

// ---------------- problem constants ----------------
#define D_DIM 3072
#define N_DIM 8192
#define B_DIM 2

#define TM 128            // CTA M tile (d)
#define TN 128            // CTA N tile (n)
#define TK 64             // K tile (halves) = 128B per row
#define STAGES 3
#define NK (N_DIM / TK)   // 128 k iterations
#define MT (D_DIM / TM)   // 24
#define NT (N_DIM / TN)   // 64

#define TOTAL_TILES (B_DIM * MT * NT)  // 3072
#define MAIN_TILES  3040               // uniform full tiles (10 exact waves of 304)
#define REM_TILES   (TOTAL_TILES - MAIN_TILES)  // 32
#define KSPLIT      8
#define NK_PART     (NK / KSPLIT)      // 16
#define REM_CTAS    (REM_TILES * KSPLIT)  // 256
#define GRID_TOTAL  (MAIN_TILES + REM_CTAS) // 3296

#define ROWH 72                           // padded row (halves): conflict-free ldmatrix
#define TILE_H (128 * ROWH)               // 9216 halves per 128-row tile
#define STAGE_H (2 * TILE_H)              // A + B per stage = 36864 B
#define SMEM_BYTES (STAGES * STAGE_H * 2) // 110592 B -> 2 CTAs/SM

// cvt grid split: blocks < CVT_X_BLOCKS sweep x, rest sweep adj (balanced by element count)
#define CVT_BLOCKS   6080
#define CVT_X_BLOCKS 1664

// fp16 scratch copies of the inputs (zero-init .bss; no runtime allocation)
__device__ __half g_xh[(size_t)B_DIM * D_DIM * N_DIM];
__device__ __half g_adjh[(size_t)B_DIM * N_DIM * N_DIM];
// split-K partials + arrival counters for the 32 remainder tiles
__device__ float g_part[(size_t)REM_TILES * KSPLIT * TM * TN];
__device__ int   g_cnt[REM_TILES];

// ---------------- PTX helpers ----------------
__device__ __forceinline__ uint32_t smem_u32(const void* p) {
    uint32_t a;
    asm("{ .reg .u64 t; cvta.to.shared.u64 t, %1; cvt.u32.u64 %0, t; }" : "=r"(a) : "l"(p));
    return a;
}
__device__ __forceinline__ void cp_async16(uint32_t saddr, const void* gaddr) {
    asm volatile("cp.async.cg.shared.global [%0], [%1], 16;" :: "r"(saddr), "l"(gaddr) : "memory");
}
#define CP_COMMIT() asm volatile("cp.async.commit_group;" ::: "memory")
#define CP_WAIT(n)  asm volatile("cp.async.wait_group %0;" :: "n"(n) : "memory")

__device__ __forceinline__ void ldmatrix_x4(uint32_t* r, uint32_t addr) {
    asm volatile("ldmatrix.sync.aligned.m8n8.x4.shared.b16 {%0,%1,%2,%3}, [%4];"
        : "=r"(r[0]), "=r"(r[1]), "=r"(r[2]), "=r"(r[3]) : "r"(addr));
}
__device__ __forceinline__ void mma_f16(float& c0, float& c1, float& c2, float& c3,
                                        uint32_t a0, uint32_t a1, uint32_t a2, uint32_t a3,
                                        uint32_t b0, uint32_t b1) {
    asm volatile(
        "mma.sync.aligned.m16n8k16.row.col.f32.f16.f16.f32 "
        "{%0,%1,%2,%3}, {%4,%5,%6,%7}, {%8,%9}, {%0,%1,%2,%3};"
        : "+f"(c0), "+f"(c1), "+f"(c2), "+f"(c3)
        : "r"(a0), "r"(a1), "r"(a2), "r"(a3), "r"(b0), "r"(b1));
}
__device__ __forceinline__ uint32_t pack_h2(float lo, float hi) {
    uint32_t u;
    asm("cvt.rn.f16x2.f32 %0, %1, %2;" : "=r"(u) : "f"(hi), "f"(lo));
    return u;
}

// ---------------- prepass: fp32 -> fp16, grid statically split per tensor ----------------
__global__ void __launch_bounds__(256)
cvt_f2h_both_kernel(const float* __restrict__ x, __half* __restrict__ xh, size_t nx,
                    const float* __restrict__ adj, __half* __restrict__ adjh, size_t na)
{
    // reset rem-tile arrival counters (runs before the GEMM in stream order)
    if (blockIdx.x == 0 && threadIdx.x < REM_TILES)
        g_cnt[threadIdx.x] = 0;

    const float* src;
    __half* dst;
    size_t n8, idx, stride;
    if (blockIdx.x < CVT_X_BLOCKS) {
        src = x;   dst = xh;   n8 = nx / 8;
        idx = (size_t)blockIdx.x * blockDim.x + threadIdx.x;
        stride = (size_t)CVT_X_BLOCKS * blockDim.x;
    } else {
        src = adj; dst = adjh; n8 = na / 8;
        idx = (size_t)(blockIdx.x - CVT_X_BLOCKS) * blockDim.x + threadIdx.x;
        stride = (size_t)(CVT_BLOCKS - CVT_X_BLOCKS) * blockDim.x;
    }
    for (; idx < n8; idx += stride) {
        const size_t i = idx * 8;
        float4 f0 = *reinterpret_cast<const float4*>(src + i);
        float4 f1 = *reinterpret_cast<const float4*>(src + i + 4);
        uint4 v;
        v.x = pack_h2(f0.x, f0.y);
        v.y = pack_h2(f0.z, f0.w);
        v.z = pack_h2(f1.x, f1.y);
        v.w = pack_h2(f1.z, f1.w);
        *reinterpret_cast<uint4*>(dst + i) = v;
    }
}

// ---------------- shared GEMM body (R10/R13 proven version) ----------------
struct GemmCtx {
    uint32_t sA_st, sB_st, aOff, bOff, sbase;
    const __half* gA;
    const __half* gB;
};

__device__ __forceinline__ void gemm_tile(const GemmCtx& cx, int kbeg, int kend,
                                          float (&acc)[4][8][4])
{
    const uint32_t sbase = cx.sbase;
    // prologue
    #pragma unroll
    for (int s = 0; s < STAGES - 1; s++) {
        const size_t k0 = (size_t)(kbeg + s) * TK;
        #pragma unroll
        for (int i = 0; i < 8; i++) {
            cp_async16(cx.sA_st + (uint32_t)(s * STAGE_H + i * 16 * ROWH) * 2, cx.gA + k0 + (size_t)i * 16 * N_DIM);
            cp_async16(cx.sB_st + (uint32_t)(s * STAGE_H + i * 16 * ROWH) * 2, cx.gB + k0 + (size_t)i * 16 * N_DIM);
        }
        CP_COMMIT();
    }
    CP_WAIT(STAGES - 2);
    __syncthreads();

    uint32_t af[2][4][4];
    uint32_t bf[2][4][4];

    // preload kb=0 of first stage
    {
        const uint32_t aBase = sbase + cx.aOff;
        const uint32_t bBase = sbase + cx.bOff;
        #pragma unroll
        for (int mi = 0; mi < 4; mi++)
            ldmatrix_x4(af[0][mi], aBase + (uint32_t)(mi * 16 * ROWH * 2));
        #pragma unroll
        for (int np = 0; np < 4; np++)
            ldmatrix_x4(bf[0][np], bBase + (uint32_t)(np * 16 * ROWH * 2));
    }

    for (int k = kbeg; k < kend; k++) {
        const int cur = (k - kbeg) % STAGES;
        const bool do_pref = (k + STAGES - 1 < kend);
        const int s = (k - kbeg + STAGES - 1) % STAGES;
        const size_t k0 = (size_t)(k + STAGES - 1) * TK;

        const uint32_t aBase = sbase + (uint32_t)(cur * STAGE_H) * 2 + cx.aOff;
        const uint32_t bBase = sbase + (uint32_t)(cur * STAGE_H) * 2 + cx.bOff;

        #pragma unroll
        for (int kb = 0; kb < 4; kb++) {
            const int cb = kb & 1;
            const int nb = cb ^ 1;

            if (kb < 3) {
                const uint32_t kByte = (uint32_t)((kb + 1) * 16 * 2);
                #pragma unroll
                for (int mi = 0; mi < 4; mi++)
                    ldmatrix_x4(af[nb][mi], aBase + (uint32_t)(mi * 16 * ROWH * 2) + kByte);
                #pragma unroll
                for (int np = 0; np < 4; np++)
                    ldmatrix_x4(bf[nb][np], bBase + (uint32_t)(np * 16 * ROWH * 2) + kByte);
            }

            #pragma unroll
            for (int mi = 0; mi < 4; mi++)
                #pragma unroll
                for (int np = 0; np < 4; np++) {
                    mma_f16(acc[mi][2*np][0], acc[mi][2*np][1], acc[mi][2*np][2], acc[mi][2*np][3],
                            af[cb][mi][0], af[cb][mi][1], af[cb][mi][2], af[cb][mi][3],
                            bf[cb][np][0], bf[cb][np][1]);
                    mma_f16(acc[mi][2*np+1][0], acc[mi][2*np+1][1], acc[mi][2*np+1][2], acc[mi][2*np+1][3],
                            af[cb][mi][0], af[cb][mi][1], af[cb][mi][2], af[cb][mi][3],
                            bf[cb][np][2], bf[cb][np][3]);
                }

            // spread next-stage cp.asyncs across kb steps, after this kb's MMAs
            if (do_pref) {
                #pragma unroll
                for (int i = 0; i < 4; i++) {
                    const int r = (kb & 1) * 4 + i;
                    if (kb < 2)
                        cp_async16(cx.sA_st + (uint32_t)(s * STAGE_H + r * 16 * ROWH) * 2,
                                   cx.gA + k0 + (size_t)r * 16 * N_DIM);
                    else
                        cp_async16(cx.sB_st + (uint32_t)(s * STAGE_H + r * 16 * ROWH) * 2,
                                   cx.gB + k0 + (size_t)r * 16 * N_DIM);
                }
            }
        }
        CP_COMMIT();

        CP_WAIT(STAGES - 2);
        __syncthreads();

        if (k + 1 < kend) {
            const int nxt = (k + 1 - kbeg) % STAGES;
            const uint32_t aB2 = sbase + (uint32_t)(nxt * STAGE_H) * 2 + cx.aOff;
            const uint32_t bB2 = sbase + (uint32_t)(nxt * STAGE_H) * 2 + cx.bOff;
            #pragma unroll
            for (int mi = 0; mi < 4; mi++)
                ldmatrix_x4(af[0][mi], aB2 + (uint32_t)(mi * 16 * ROWH * 2));
            #pragma unroll
            for (int np = 0; np < 4; np++)
                ldmatrix_x4(bf[0][np], bB2 + (uint32_t)(np * 16 * ROWH * 2));
        }
    }
}

__device__ __forceinline__ void make_ctx(GemmCtx& cx, uint32_t sbase, int tid,
                                         int b, int d0, int n0, int wm, int wn)
{
    const int lane = tid & 31;
    const int crow = tid >> 3;
    const int cc   = tid & 7;
    cx.sbase = sbase;
    cx.gA = g_xh   + ((size_t)b * D_DIM + d0 + crow) * N_DIM + cc * 8;
    cx.gB = g_adjh + ((size_t)b * N_DIM + n0 + crow) * N_DIM + cc * 8;
    cx.sA_st = sbase + (uint32_t)(crow * ROWH + cc * 8) * 2;
    cx.sB_st = cx.sA_st + TILE_H * 2;
    cx.aOff = (uint32_t)(((wm + (lane & 15)) * ROWH + (lane >> 4) * 8) * 2);
    cx.bOff = (uint32_t)(((wn + ((lane >> 4) << 3) + (lane & 7)) * ROWH
                          + ((lane >> 3) & 1) * 8) * 2) + TILE_H * 2;
}

// ---------------- merged GEMM kernel: main tiles first, rem CTAs last (with fused reduce) ----------------
__global__ void __launch_bounds__(128, 2)
gcn_f16_mma_kernel(float* __restrict__ out)
{
    extern __shared__ __half smem[];
    __shared__ int s_last;
    const uint32_t sbase = smem_u32(smem);
    const int tid = threadIdx.x;
    const int wid = tid >> 5;
    const int lane = tid & 31;
    const int wm = (wid & 1) * 64;
    const int wn = (wid >> 1) * 64;

    const int bx = blockIdx.x;
    const bool is_rem = (bx >= MAIN_TILES);

    int tile, kbeg, kend;
    if (is_rem) {
        const int rix = bx - MAIN_TILES;     // 0..255
        tile = MAIN_TILES + (rix >> 3);      // 3040..3071
        const int kp = rix & 7;
        kbeg = kp * NK_PART;
        kend = kbeg + NK_PART;
    } else {
        tile = bx;                           // 0..3039
        kbeg = 0;
        kend = NK;
    }

    const int mt = tile % MT;
    const int nt = (tile / MT) % NT;
    const int b  = tile / (MT * NT);
    const int d0 = mt * TM;
    const int n0 = nt * TN;

    GemmCtx cx;
    make_ctx(cx, sbase, tid, b, d0, n0, wm, wn);

    float acc[4][8][4];
    #pragma unroll
    for (int i = 0; i < 4; i++)
        #pragma unroll
        for (int j = 0; j < 8; j++)
            #pragma unroll
            for (int r = 0; r < 4; r++) acc[i][j][r] = 0.0f;

    gemm_tile(cx, kbeg, kend, acc);

    if (is_rem) {
        // store partials row-major [128][128] into g_part[rix]
        const int rix = bx - MAIN_TILES;
        const int t  = rix >> 3;
        float* pb = g_part + (size_t)rix * (TM * TN);
        #pragma unroll
        for (int mi = 0; mi < 4; mi++) {
            const int r0 = wm + mi * 16 + (lane >> 2);
            #pragma unroll
            for (int ni = 0; ni < 8; ni++) {
                const int c = wn + ni * 8 + (lane & 3) * 2;
                float2 v0 = make_float2(acc[mi][ni][0], acc[mi][ni][1]);
                float2 v1 = make_float2(acc[mi][ni][2], acc[mi][ni][3]);
                *reinterpret_cast<float2*>(pb + (size_t)r0 * TN + c) = v0;
                *reinterpret_cast<float2*>(pb + (size_t)(r0 + 8) * TN + c) = v1;
            }
        }

        // threadfence-reduction: 8th arriver for this tile sums all partials into out
        __threadfence();
        __syncthreads();
        if (tid == 0)
            s_last = (atomicAdd(&g_cnt[t], 1) == KSPLIT - 1);
        __syncthreads();

        if (s_last) {
            const float* base = g_part + (size_t)t * KSPLIT * (TM * TN);
            float* ob = out + ((size_t)b * D_DIM + d0) * N_DIM + n0;
            // 16384 elems / 128 threads = 32 float4 per thread
            for (int e4 = tid; e4 < TM * TN / 4; e4 += 128) {
                const int e = e4 * 4;
                float4 sv = *reinterpret_cast<const float4*>(base + e);
                #pragma unroll
                for (int p = 1; p < KSPLIT; p++) {
                    float4 v = *reinterpret_cast<const float4*>(base + (size_t)p * (TM * TN) + e);
                    sv.x += v.x; sv.y += v.y; sv.z += v.z; sv.w += v.w;
                }
                const int row = e / TN;
                const int col = e % TN;
                *reinterpret_cast<float4*>(ob + (size_t)row * N_DIM + col) = sv;
            }
        }
    } else {
        float* ob = out + ((size_t)b * D_DIM) * N_DIM;
        #pragma unroll
        for (int mi = 0; mi < 4; mi++) {
            const int r0 = d0 + wm + mi * 16 + (lane >> 2);
            #pragma unroll
            for (int ni = 0; ni < 8; ni++) {
                const int c = n0 + wn + ni * 8 + (lane & 3) * 2;
                float2 v0 = make_float2(acc[mi][ni][0], acc[mi][ni][1]);
                float2 v1 = make_float2(acc[mi][ni][2], acc[mi][ni][3]);
                *reinterpret_cast<float2*>(ob + (size_t)r0 * N_DIM + c) = v0;
                *reinterpret_cast<float2*>(ob + (size_t)(r0 + 8) * N_DIM + c) = v1;
            }
        }
    }
}

// ---------------- host launch ----------------
extern "C" void kernel_launch(void* const* d_in, const int* in_sizes, int n_in,
                              void* d_out, int out_size)
{
    const float* x;
    const float* adj;
    if (in_sizes[0] == B_DIM * D_DIM * N_DIM) {
        x = (const float*)d_in[0]; adj = (const float*)d_in[1];
    } else {
        x = (const float*)d_in[1]; adj = (const float*)d_in[0];
    }

    __half* xh;
    __half* adjh;
    cudaGetSymbolAddress((void**)&xh, g_xh);
    cudaGetSymbolAddress((void**)&adjh, g_adjh);

    const size_t nx = (size_t)B_DIM * D_DIM * N_DIM;
    const size_t na = (size_t)B_DIM * N_DIM * N_DIM;
    cvt_f2h_both_kernel<<<CVT_BLOCKS, 256>>>(x, xh, nx, adj, adjh, na);

    cudaFuncSetAttribute(gcn_f16_mma_kernel, cudaFuncAttributeMaxDynamicSharedMemorySize, SMEM_BYTES);
    gcn_f16_mma_kernel<<<GRID_TOTAL, 128, SMEM_BYTES>>>((float*)d_out);
}